// round 1
// baseline (speedup 1.0000x reference)
#include <cuda_runtime.h>
#include <math.h>

#define NN 100000
#define EE 1600000

// ---------------- scratch (static device globals; no allocations) ----------
__device__ float g_h[NN * 64];            // node features (25.6 MB)
__device__ float g_hAB[NN * 128];         // per-node edge-MLP projections (51.2 MB)
__device__ float g_SH[NN * 64];           // scatter-sum of edge hidden (25.6 MB)
__device__ float g_deg[NN];               // in-degree (float)
__device__ float g_WAB[2][64 * 128];      // [A | B] combined edge weights
__device__ float g_P[2][192];             // pos_diff projection rows of eW0
__device__ float g_M[2][64 * 64];         // eW1 @ nW0b
__device__ float g_c[2][64];              // eb1 @ nW0b
__device__ int   g_i32;                   // 1 if edge_index is int32

__device__ __forceinline__ float elu1(float x) {
    return x > 0.f ? x : expm1f(x);
}

__device__ __forceinline__ void fma16(float (&acc)[4][4], float4 xv, float4 wv) {
    float xr[4] = {xv.x, xv.y, xv.z, xv.w};
    float wr[4] = {wv.x, wv.y, wv.z, wv.w};
#pragma unroll
    for (int i = 0; i < 4; i++)
#pragma unroll
        for (int j = 0; j < 4; j++) acc[i][j] = fmaf(xr[i], wr[j], acc[i][j]);
}

// ---------------- prep: derived weights (tiny) ------------------------------
__global__ void prep_kernel(const float* __restrict__ eW0,
                            const float* __restrict__ eW1,
                            const float* __restrict__ nW0,
                            const float* __restrict__ eb1) {
    int l = blockIdx.x;
    int tid = threadIdx.x;
    const float* w0 = eW0 + l * 195 * 64;
    // WAB: col j<64 -> Wn + Wd ; col j>=64 -> Wo - Wd
    for (int idx = tid; idx < 64 * 128; idx += 256) {
        int k = idx >> 7, j = idx & 127;
        float v;
        if (j < 64) v = w0[k * 64 + j] + w0[(128 + k) * 64 + j];
        else { int j2 = j - 64; v = w0[(64 + k) * 64 + j2] - w0[(128 + k) * 64 + j2]; }
        g_WAB[l][idx] = v;
    }
    for (int idx = tid; idx < 192; idx += 256)
        g_P[l][idx] = w0[192 * 64 + idx];
    const float* e1  = eW1 + l * 4096;
    const float* n0b = nW0 + l * 8192 + 64 * 64;   // rows 64..127 of nW0
    for (int idx = tid; idx < 4096; idx += 256) {
        int r = idx >> 6, cc = idx & 63;
        float s = 0.f;
        for (int k = 0; k < 64; k++) s += e1[r * 64 + k] * n0b[k * 64 + cc];
        g_M[l][idx] = s;
    }
    const float* b1e = eb1 + l * 64;
    for (int idx = tid; idx < 64; idx += 256) {
        float s = 0.f;
        for (int k = 0; k < 64; k++) s += b1e[k] * n0b[k * 64 + idx];
        g_c[l][idx] = s;
    }
}

// ---------------- zero / detect / degree ------------------------------------
__global__ void zero_kernel(int with_deg) {
    int i = blockIdx.x * 256 + threadIdx.x;
    int stride = gridDim.x * 256;
    for (int idx = i; idx < NN * 64; idx += stride) g_SH[idx] = 0.f;
    if (with_deg) {
        for (int idx = i; idx < NN; idx += stride) g_deg[idx] = 0.f;
        if (i == 0) g_i32 = 0;
    }
}

// if int64: odd 32-bit words (high halves) are all zero. Any nonzero -> int32.
__global__ void detect_kernel(const unsigned* __restrict__ ei) {
    int i = blockIdx.x * 256 + threadIdx.x;
    if (i < EE) {
        if (ei[2 * i + 1] != 0u) g_i32 = 1;
    }
}

__device__ __forceinline__ int load_dst(const void* ei, int e) {
    if (g_i32) return ((const int*)ei)[EE + e];
    return (int)((const long long*)ei)[EE + e];
}
__device__ __forceinline__ int load_src(const void* ei, int e) {
    if (g_i32) return ((const int*)ei)[e];
    return (int)((const long long*)ei)[e];
}

__global__ __launch_bounds__(256) void deg_kernel(const void* __restrict__ ei) {
    int e = blockIdx.x * 256 + threadIdx.x;
    if (e < EE) atomicAdd(&g_deg[load_dst(ei, e)], 1.0f);
}

// ---------------- two-layer node MLP (fused) --------------------------------
// out = [elu(X @ W1 + b1 (+ deg*c))] @ W2 + b2   (+= if RESID)
constexpr int MLP_NODES   = 48;
constexpr int MLP_NPAD    = 52;
constexpr int MLP_THREADS = 192;

template <int K1, int J2, bool TWO_IN, bool DEG, bool RESID>
__global__ __launch_bounds__(MLP_THREADS)
void mlp2_kernel(const float* __restrict__ X1, const float* __restrict__ X2,
                 const float* __restrict__ W1a, const float* __restrict__ W1b,
                 const float* __restrict__ b1,  const float* __restrict__ cvec,
                 const float* __restrict__ W2,  const float* __restrict__ b2,
                 float* __restrict__ out) {
    __shared__ float Xs[K1][MLP_NPAD];
    __shared__ float Hs[64][MLP_NPAD];

    const int tid = threadIdx.x;
    const int tj = tid & 15;
    const int tn = tid >> 4;            // 0..11
    const int base = blockIdx.x * MLP_NODES;
    const int n0 = tn * 4;
    const int j0 = tj * 4;

    // stage X transposed: Xs[k][n]
    for (int idx = tid; idx < MLP_NODES * K1; idx += MLP_THREADS) {
        int n = idx / K1, k = idx - n * K1;
        int gn = base + n;
        float v = 0.f;
        if (gn < NN) {
            if constexpr (TWO_IN)
                v = (k < 64) ? X1[gn * 64 + k] : X2[gn * 64 + (k - 64)];
            else
                v = X1[gn * K1 + k];
        }
        Xs[k][n] = v;
    }
    __syncthreads();

    float acc[4][4];
#pragma unroll
    for (int i = 0; i < 4; i++)
#pragma unroll
        for (int j = 0; j < 4; j++) acc[i][j] = 0.f;

    constexpr int KA = TWO_IN ? 64 : K1;
#pragma unroll 4
    for (int k = 0; k < KA; k++) {
        float4 xv = *(const float4*)&Xs[k][n0];
        float4 wv = __ldg((const float4*)&W1a[k * 64 + j0]);
        fma16(acc, xv, wv);
    }
    if constexpr (TWO_IN) {
#pragma unroll 4
        for (int k = 0; k < 64; k++) {
            float4 xv = *(const float4*)&Xs[64 + k][n0];
            float4 wv = __ldg((const float4*)&W1b[k * 64 + j0]);
            fma16(acc, xv, wv);
        }
    }

    float4 bb = __ldg((const float4*)&b1[j0]);
    float bj[4] = {bb.x, bb.y, bb.z, bb.w};
    float cj[4] = {0, 0, 0, 0}, dg[4] = {0, 0, 0, 0};
    if constexpr (DEG) {
        float4 cv = __ldg((const float4*)&cvec[j0]);
        cj[0] = cv.x; cj[1] = cv.y; cj[2] = cv.z; cj[3] = cv.w;
#pragma unroll
        for (int i = 0; i < 4; i++) {
            int gn = base + n0 + i;
            dg[i] = (gn < NN) ? g_deg[gn] : 0.f;
        }
    }
    float hid[4][4];
#pragma unroll
    for (int i = 0; i < 4; i++)
#pragma unroll
        for (int j = 0; j < 4; j++) {
            float v = acc[i][j] + bj[j];
            if constexpr (DEG) v = fmaf(dg[i], cj[j], v);
            hid[i][j] = elu1(v);
        }
#pragma unroll
    for (int jj = 0; jj < 4; jj++) {
        float4 hv = make_float4(hid[0][jj], hid[1][jj], hid[2][jj], hid[3][jj]);
        *(float4*)&Hs[j0 + jj][n0] = hv;
    }
    __syncthreads();

    if constexpr (J2 == 64) {
        float a2[4][4];
#pragma unroll
        for (int i = 0; i < 4; i++)
#pragma unroll
            for (int j = 0; j < 4; j++) a2[i][j] = 0.f;
#pragma unroll 4
        for (int k = 0; k < 64; k++) {
            float4 xv = *(const float4*)&Hs[k][n0];
            float4 wv = __ldg((const float4*)&W2[k * 64 + j0]);
            fma16(a2, xv, wv);
        }
        float4 b2v = __ldg((const float4*)&b2[j0]);
#pragma unroll
        for (int i = 0; i < 4; i++) {
            int gn = base + n0 + i;
            if (gn < NN) {
                float4 o;
                o.x = a2[i][0] + b2v.x;
                o.y = a2[i][1] + b2v.y;
                o.z = a2[i][2] + b2v.z;
                o.w = a2[i][3] + b2v.w;
                if constexpr (RESID) {
                    float4 prev = *(const float4*)&out[gn * 64 + j0];
                    o.x += prev.x; o.y += prev.y; o.z += prev.z; o.w += prev.w;
                }
                *(float4*)&out[gn * 64 + j0] = o;
            }
        }
    } else {  // J2 == 3 (decoder): each tj covers 4 k2 values; reduce across tj
        float a3[4][3] = {};
#pragma unroll
        for (int kk = 0; kk < 4; kk++) {
            int k = j0 + kk;
            float4 hv = *(const float4*)&Hs[k][n0];
            float hr[4] = {hv.x, hv.y, hv.z, hv.w};
#pragma unroll
            for (int j = 0; j < 3; j++) {
                float w = __ldg(&W2[k * 3 + j]);
#pragma unroll
                for (int i = 0; i < 4; i++) a3[i][j] = fmaf(hr[i], w, a3[i][j]);
            }
        }
#pragma unroll
        for (int off = 8; off; off >>= 1)
#pragma unroll
            for (int i = 0; i < 4; i++)
#pragma unroll
                for (int j = 0; j < 3; j++)
                    a3[i][j] += __shfl_down_sync(0xffffffffu, a3[i][j], off, 16);
        if (tj == 0) {
#pragma unroll
            for (int i = 0; i < 4; i++) {
                int gn = base + n0 + i;
                if (gn < NN)
#pragma unroll
                    for (int j = 0; j < 3; j++)
                        out[gn * 3 + j] = a3[i][j] + __ldg(&b2[j]);
            }
        }
    }
}

// ---------------- hAB = h @ WAB (64 -> 128) ---------------------------------
constexpr int HAB_NODES = 32;
constexpr int HAB_NPAD  = 36;

__global__ __launch_bounds__(256) void hab_kernel(const float* __restrict__ Wab) {
    __shared__ float Xs[64][HAB_NPAD];
    const int tid = threadIdx.x;
    const int tj = tid & 31;     // 32 j-quads -> 128 outputs
    const int tn = tid >> 5;     // 8 node-quads -> 32 nodes
    const int base = blockIdx.x * HAB_NODES;

    for (int idx = tid; idx < HAB_NODES * 64; idx += 256) {
        int n = idx >> 6, k = idx & 63;
        int gn = base + n;
        Xs[k][n] = (gn < NN) ? g_h[gn * 64 + k] : 0.f;
    }
    __syncthreads();

    const int n0 = tn * 4, j0 = tj * 4;
    float acc[4][4];
#pragma unroll
    for (int i = 0; i < 4; i++)
#pragma unroll
        for (int j = 0; j < 4; j++) acc[i][j] = 0.f;
#pragma unroll 4
    for (int k = 0; k < 64; k++) {
        float4 xv = *(const float4*)&Xs[k][n0];
        float4 wv = __ldg((const float4*)&Wab[k * 128 + j0]);
        fma16(acc, xv, wv);
    }
#pragma unroll
    for (int i = 0; i < 4; i++) {
        int gn = base + n0 + i;
        if (gn < NN) {
            float4 o = make_float4(acc[i][0], acc[i][1], acc[i][2], acc[i][3]);
            *(float4*)&g_hAB[gn * 128 + j0] = o;
        }
    }
}

// ---------------- edge pass: gather + elu + vector scatter-add --------------
__global__ __launch_bounds__(256) void edge_kernel(const void* __restrict__ ei,
                                                   const float* __restrict__ pos,
                                                   const float* __restrict__ eb0,
                                                   int layer) {
    int t = blockIdx.x * 256 + threadIdx.x;
    int e = t >> 4, c4 = t & 15;
    if (e >= EE) return;
    int s = load_src(ei, e);
    int d = load_dst(ei, e);

    float pd0 = __ldg(&pos[s * 3 + 0]) - __ldg(&pos[d * 3 + 0]);
    float pd1 = __ldg(&pos[s * 3 + 1]) - __ldg(&pos[d * 3 + 1]);
    float pd2 = __ldg(&pos[s * 3 + 2]) - __ldg(&pos[d * 3 + 2]);

    const int j0 = c4 * 4;
    const float* P = g_P[layer];
    float4 p0 = *(const float4*)&P[j0];
    float4 p1 = *(const float4*)&P[64 + j0];
    float4 p2 = *(const float4*)&P[128 + j0];
    float4 bb = __ldg((const float4*)&eb0[layer * 64 + j0]);

    float4 va = *(const float4*)&g_hAB[s * 128 + j0];
    float4 vb = *(const float4*)&g_hAB[d * 128 + 64 + j0];

    float v0 = elu1(va.x + vb.x + bb.x + fmaf(pd0, p0.x, fmaf(pd1, p1.x, pd2 * p2.x)));
    float v1 = elu1(va.y + vb.y + bb.y + fmaf(pd0, p0.y, fmaf(pd1, p1.y, pd2 * p2.y)));
    float v2 = elu1(va.z + vb.z + bb.z + fmaf(pd0, p0.z, fmaf(pd1, p1.z, pd2 * p2.z)));
    float v3 = elu1(va.w + vb.w + bb.w + fmaf(pd0, p0.w, fmaf(pd1, p1.w, pd2 * p2.w)));

    float* dstp = &g_SH[d * 64 + j0];
    asm volatile("red.global.add.v4.f32 [%0], {%1, %2, %3, %4};"
                 :: "l"(dstp), "f"(v0), "f"(v1), "f"(v2), "f"(v3)
                 : "memory");
}

// ---------------- launch ----------------------------------------------------
extern "C" void kernel_launch(void* const* d_in, const int* in_sizes, int n_in,
                              void* d_out, int out_size) {
    const float* x      = (const float*)d_in[0];
    const float* pos    = (const float*)d_in[1];
    const void*  ei     = d_in[2];
    const float* enc_W0 = (const float*)d_in[3];
    const float* enc_b0 = (const float*)d_in[4];
    const float* enc_W1 = (const float*)d_in[5];
    const float* enc_b1 = (const float*)d_in[6];
    const float* dec_W0 = (const float*)d_in[7];
    const float* dec_b0 = (const float*)d_in[8];
    const float* dec_W1 = (const float*)d_in[9];
    const float* dec_b1 = (const float*)d_in[10];
    const float* eW0    = (const float*)d_in[11];
    const float* eb0    = (const float*)d_in[12];
    const float* eW1    = (const float*)d_in[13];
    const float* eb1    = (const float*)d_in[14];
    const float* nW0    = (const float*)d_in[15];
    const float* nb0    = (const float*)d_in[16];
    const float* nW1    = (const float*)d_in[17];
    const float* nb1    = (const float*)d_in[18];
    float* out = (float*)d_out;

    float *p_h, *p_SH, *p_WAB, *p_M, *p_c;
    cudaGetSymbolAddress((void**)&p_h,   g_h);
    cudaGetSymbolAddress((void**)&p_SH,  g_SH);
    cudaGetSymbolAddress((void**)&p_WAB, g_WAB);
    cudaGetSymbolAddress((void**)&p_M,   g_M);
    cudaGetSymbolAddress((void**)&p_c,   g_c);

    const int MLP_GRID = (NN + MLP_NODES - 1) / MLP_NODES;

    prep_kernel<<<2, 256>>>(eW0, eW1, nW0, eb1);
    zero_kernel<<<4096, 256>>>(1);
    detect_kernel<<<(EE + 255) / 256, 256>>>((const unsigned*)ei);
    deg_kernel<<<(EE + 255) / 256, 256>>>(ei);

    // encoder: h = elu(x@enc_W0+b0) @ enc_W1 + b1
    mlp2_kernel<3, 64, false, false, false><<<MLP_GRID, MLP_THREADS>>>(
        x, nullptr, enc_W0, nullptr, enc_b0, nullptr, enc_W1, enc_b1, p_h);

    for (int l = 0; l < 2; l++) {
        if (l) zero_kernel<<<4096, 256>>>(0);
        hab_kernel<<<(NN + HAB_NODES - 1) / HAB_NODES, 256>>>(p_WAB + l * 64 * 128);
        edge_kernel<<<(EE * 16 + 255) / 256, 256>>>(ei, pos, eb0, l);
        // node update: h += [elu(h@nW0a + SH@M + deg*c + nb0)] @ nW1 + nb1
        mlp2_kernel<128, 64, true, true, true><<<MLP_GRID, MLP_THREADS>>>(
            p_h, p_SH, nW0 + l * 128 * 64, p_M + l * 64 * 64, nb0 + l * 64,
            p_c + l * 64, nW1 + l * 64 * 64, nb1 + l * 64, p_h);
    }

    // decoder
    mlp2_kernel<64, 3, false, false, false><<<MLP_GRID, MLP_THREADS>>>(
        p_h, nullptr, dec_W0, nullptr, dec_b0, nullptr, dec_W1, dec_b1, out);
}

// round 6
// speedup vs baseline: 1.0350x; 1.0350x over previous
#include <cuda_runtime.h>
#include <math.h>

#define NN 100000
#define EE 1600000

typedef unsigned int u32;

// ---------------- scratch (static device globals; no allocations) ----------
__device__ float g_h[NN * 64];            // node features (25.6 MB)
__device__ float g_hAB[NN * 128];         // per-node edge-MLP projections (51.2 MB)
__device__ float g_SH[NN * 64];           // scatter-sum of edge hidden (25.6 MB)
__device__ float g_deg[NN];               // in-degree (float)
__device__ float g_WAB[2][64 * 128];      // [A | B] combined edge weights
__device__ float g_P[2][192];             // pos_diff projection rows of eW0
__device__ float g_M[2][64 * 64];         // eW1 @ nW0b
__device__ float g_c[2][64];              // eb1 @ nW0b
__device__ int   g_i32;                   // 1 if edge_index is int32

__device__ __forceinline__ float elu1(float x) {
    return x > 0.f ? x : expm1f(x);
}
__device__ __forceinline__ u32 f2tf32(float f) {
    u32 r; asm("cvt.rna.tf32.f32 %0, %1;" : "=r"(r) : "f"(f)); return r;
}
__device__ __forceinline__ float tf32f(float f) {
    return __uint_as_float(f2tf32(f));
}

// mma.sync m16n8k8 tf32 (legacy tensor-core path; compiles for base sm_103)
__device__ __forceinline__ void mma8(float* c, u32 a0, u32 a1, u32 a2, u32 a3,
                                     u32 b0, u32 b1) {
    asm volatile(
        "mma.sync.aligned.m16n8k8.row.col.f32.tf32.tf32.f32 "
        "{%0,%1,%2,%3}, {%4,%5,%6,%7}, {%8,%9}, {%0,%1,%2,%3};"
        : "+f"(c[0]), "+f"(c[1]), "+f"(c[2]), "+f"(c[3])
        : "r"(a0), "r"(a1), "r"(a2), "r"(a3), "r"(b0), "r"(b1));
}

// ---------------- prep: derived weights (tiny) ------------------------------
__global__ void prep_kernel(const float* __restrict__ eW0,
                            const float* __restrict__ eW1,
                            const float* __restrict__ nW0,
                            const float* __restrict__ eb1) {
    int l = blockIdx.x;
    int tid = threadIdx.x;
    const float* w0 = eW0 + l * 195 * 64;
    for (int idx = tid; idx < 64 * 128; idx += 256) {
        int k = idx >> 7, j = idx & 127;
        float v;
        if (j < 64) v = w0[k * 64 + j] + w0[(128 + k) * 64 + j];
        else { int j2 = j - 64; v = w0[(64 + k) * 64 + j2] - w0[(128 + k) * 64 + j2]; }
        g_WAB[l][idx] = v;
    }
    for (int idx = tid; idx < 192; idx += 256)
        g_P[l][idx] = w0[192 * 64 + idx];
    const float* e1  = eW1 + l * 4096;
    const float* n0b = nW0 + l * 8192 + 64 * 64;
    for (int idx = tid; idx < 4096; idx += 256) {
        int r = idx >> 6, cc = idx & 63;
        float s = 0.f;
        for (int k = 0; k < 64; k++) s += e1[r * 64 + k] * n0b[k * 64 + cc];
        g_M[l][idx] = s;
    }
    const float* b1e = eb1 + l * 64;
    for (int idx = tid; idx < 64; idx += 256) {
        float s = 0.f;
        for (int k = 0; k < 64; k++) s += b1e[k] * n0b[k * 64 + idx];
        g_c[l][idx] = s;
    }
}

// ---------------- zero / detect / degree ------------------------------------
__global__ void zero_kernel(int with_deg) {
    int i = blockIdx.x * 256 + threadIdx.x;
    int stride = gridDim.x * 256;
    for (int idx = i; idx < NN * 64; idx += stride) g_SH[idx] = 0.f;
    if (with_deg) {
        for (int idx = i; idx < NN; idx += stride) g_deg[idx] = 0.f;
        if (i == 0) g_i32 = 0;
    }
}

__global__ void detect_kernel(const unsigned* __restrict__ ei) {
    int i = blockIdx.x * 256 + threadIdx.x;
    if (i < EE) {
        if (ei[2 * i + 1] != 0u) g_i32 = 1;
    }
}

__device__ __forceinline__ int load_dst(const void* ei, int e) {
    if (g_i32) return ((const int*)ei)[EE + e];
    return (int)((const long long*)ei)[EE + e];
}
__device__ __forceinline__ int load_src(const void* ei, int e) {
    if (g_i32) return ((const int*)ei)[e];
    return (int)((const long long*)ei)[e];
}

__global__ __launch_bounds__(256) void deg_kernel(const void* __restrict__ ei) {
    int e = blockIdx.x * 256 + threadIdx.x;
    if (e < EE) atomicAdd(&g_deg[load_dst(ei, e)], 1.0f);
}

// ---------------- FFMA two-layer node MLP (encoder / decoder only) ----------
constexpr int MLP_NODES   = 48;
constexpr int MLP_NPAD    = 52;
constexpr int MLP_THREADS = 192;

__device__ __forceinline__ void fma16(float (&acc)[4][4], float4 xv, float4 wv) {
    float xr[4] = {xv.x, xv.y, xv.z, xv.w};
    float wr[4] = {wv.x, wv.y, wv.z, wv.w};
#pragma unroll
    for (int i = 0; i < 4; i++)
#pragma unroll
        for (int j = 0; j < 4; j++) acc[i][j] = fmaf(xr[i], wr[j], acc[i][j]);
}

template <int K1, int J2>
__global__ __launch_bounds__(MLP_THREADS)
void mlp2_kernel(const float* __restrict__ X1,
                 const float* __restrict__ W1a,
                 const float* __restrict__ b1,
                 const float* __restrict__ W2,  const float* __restrict__ b2,
                 float* __restrict__ out) {
    __shared__ float Xs[K1][MLP_NPAD];
    __shared__ float Hs[64][MLP_NPAD];

    const int tid = threadIdx.x;
    const int tj = tid & 15;
    const int tn = tid >> 4;
    const int base = blockIdx.x * MLP_NODES;
    const int n0 = tn * 4;
    const int j0 = tj * 4;

    for (int idx = tid; idx < MLP_NODES * K1; idx += MLP_THREADS) {
        int n = idx / K1, k = idx - n * K1;
        int gn = base + n;
        Xs[k][n] = (gn < NN) ? X1[gn * K1 + k] : 0.f;
    }
    __syncthreads();

    float acc[4][4];
#pragma unroll
    for (int i = 0; i < 4; i++)
#pragma unroll
        for (int j = 0; j < 4; j++) acc[i][j] = 0.f;

#pragma unroll 4
    for (int k = 0; k < K1; k++) {
        float4 xv = *(const float4*)&Xs[k][n0];
        float4 wv = __ldg((const float4*)&W1a[k * 64 + j0]);
        fma16(acc, xv, wv);
    }

    float4 bb = __ldg((const float4*)&b1[j0]);
    float bj[4] = {bb.x, bb.y, bb.z, bb.w};
    float hid[4][4];
#pragma unroll
    for (int i = 0; i < 4; i++)
#pragma unroll
        for (int j = 0; j < 4; j++)
            hid[i][j] = elu1(acc[i][j] + bj[j]);
#pragma unroll
    for (int jj = 0; jj < 4; jj++) {
        float4 hv = make_float4(hid[0][jj], hid[1][jj], hid[2][jj], hid[3][jj]);
        *(float4*)&Hs[j0 + jj][n0] = hv;
    }
    __syncthreads();

    if constexpr (J2 == 64) {
        float a2[4][4];
#pragma unroll
        for (int i = 0; i < 4; i++)
#pragma unroll
            for (int j = 0; j < 4; j++) a2[i][j] = 0.f;
#pragma unroll 4
        for (int k = 0; k < 64; k++) {
            float4 xv = *(const float4*)&Hs[k][n0];
            float4 wv = __ldg((const float4*)&W2[k * 64 + j0]);
            fma16(a2, xv, wv);
        }
        float4 b2v = __ldg((const float4*)&b2[j0]);
#pragma unroll
        for (int i = 0; i < 4; i++) {
            int gn = base + n0 + i;
            if (gn < NN) {
                float4 o;
                o.x = a2[i][0] + b2v.x;
                o.y = a2[i][1] + b2v.y;
                o.z = a2[i][2] + b2v.z;
                o.w = a2[i][3] + b2v.w;
                *(float4*)&out[gn * 64 + j0] = o;
            }
        }
    } else {  // J2 == 3 decoder
        float a3[4][3] = {};
#pragma unroll
        for (int kk = 0; kk < 4; kk++) {
            int k = j0 + kk;
            float4 hv = *(const float4*)&Hs[k][n0];
            float hr[4] = {hv.x, hv.y, hv.z, hv.w};
#pragma unroll
            for (int j = 0; j < 3; j++) {
                float w = __ldg(&W2[k * 3 + j]);
#pragma unroll
                for (int i = 0; i < 4; i++) a3[i][j] = fmaf(hr[i], w, a3[i][j]);
            }
        }
#pragma unroll
        for (int off = 8; off; off >>= 1)
#pragma unroll
            for (int i = 0; i < 4; i++)
#pragma unroll
                for (int j = 0; j < 3; j++)
                    a3[i][j] += __shfl_down_sync(0xffffffffu, a3[i][j], off, 16);
        if (tj == 0) {
#pragma unroll
            for (int i = 0; i < 4; i++) {
                int gn = base + n0 + i;
                if (gn < NN)
#pragma unroll
                    for (int j = 0; j < 3; j++)
                        out[gn * 3 + j] = a3[i][j] + __ldg(&b2[j]);
            }
        }
    }
}

// ======================= mma.sync hAB kernel ================================
// hAB[m, 0:128] = h[m,0:64] @ WAB[64,128]; CTA = 128 rows, 8 warps x 16 rows.
constexpr int HA_STR = 68;    // 68 % 32 == 4  -> conflict-free A frags
constexpr int HW_STR = 136;   // 136 % 32 == 8 -> conflict-free B frags
constexpr int HAB_SMEMB = (128 * HA_STR + 64 * HW_STR) * 4;

__global__ __launch_bounds__(256, 1) void tm_hab_kernel(const float* __restrict__ Wab) {
    extern __shared__ float smf[];
    float* sA = smf;                       // [128][HA_STR], k = 0..63
    float* sW = smf + 128 * HA_STR;        // [64][HW_STR],  n = 0..127

    const int tid = threadIdx.x, wid = tid >> 5, lane = tid & 31;
    const int g = lane >> 2, t = lane & 3;
    const int base = blockIdx.x * 128;

    for (int idx = tid; idx < 128 * 16; idx += 256) {
        int m = idx >> 4, k0 = (idx & 15) * 4;
        int gn = base + m;
        float4 v = make_float4(0.f, 0.f, 0.f, 0.f);
        if (gn < NN) v = *(const float4*)&g_h[gn * 64 + k0];
        float* p = sA + m * HA_STR + k0;
        p[0] = tf32f(v.x); p[1] = tf32f(v.y); p[2] = tf32f(v.z); p[3] = tf32f(v.w);
    }
    for (int idx = tid; idx < 64 * 128; idx += 256) {
        int k = idx >> 7, n = idx & 127;
        sW[k * HW_STR + n] = tf32f(__ldg(&Wab[k * 128 + n]));
    }
    __syncthreads();

    const float* Aw = sA + (wid * 16) * HA_STR;
    float acc[16][4];
#pragma unroll
    for (int i = 0; i < 16; i++)
#pragma unroll
        for (int j = 0; j < 4; j++) acc[i][j] = 0.f;

#pragma unroll
    for (int ks = 0; ks < 8; ks++) {
        int k0 = ks * 8;
        u32 a0 = __float_as_uint(Aw[g * HA_STR + k0 + t]);
        u32 a1 = __float_as_uint(Aw[(g + 8) * HA_STR + k0 + t]);
        u32 a2 = __float_as_uint(Aw[g * HA_STR + k0 + t + 4]);
        u32 a3 = __float_as_uint(Aw[(g + 8) * HA_STR + k0 + t + 4]);
#pragma unroll
        for (int nt = 0; nt < 16; nt++) {
            u32 b0 = __float_as_uint(sW[(k0 + t) * HW_STR + nt * 8 + g]);
            u32 b1 = __float_as_uint(sW[(k0 + t + 4) * HW_STR + nt * 8 + g]);
            mma8(acc[nt], a0, a1, a2, a3, b0, b1);
        }
    }

    const int r0 = base + wid * 16 + g;
    const int r1 = r0 + 8;
#pragma unroll
    for (int nt = 0; nt < 16; nt++) {
        int col = nt * 8 + 2 * t;
        if (r0 < NN) *(float2*)&g_hAB[r0 * 128 + col] = make_float2(acc[nt][0], acc[nt][1]);
        if (r1 < NN) *(float2*)&g_hAB[r1 * 128 + col] = make_float2(acc[nt][2], acc[nt][3]);
    }
}

// ======================= mma.sync fused node-update kernel ==================
// h += elu([h|SH] @ W1 + deg*c + b0) @ W2 + b1   (K1=128 -> N=64, K2=64 -> N=64)
constexpr int NA_STR = 132;   // 132 % 32 == 4
constexpr int NW_STR = 72;    // 72  % 32 == 8
constexpr int ND_SMEMB = (128 * NA_STR + 128 * NW_STR + 64 * NW_STR) * 4;

__global__ __launch_bounds__(256, 1) void tm_node_kernel(
    const float* __restrict__ nW0l, const float* __restrict__ Ml,
    const float* __restrict__ nb0l, const float* __restrict__ cl,
    const float* __restrict__ nW1l, const float* __restrict__ nb1l) {
    extern __shared__ float smf[];
    float* sA  = smf;                                  // [128][NA_STR]
    float* sW1 = smf + 128 * NA_STR;                   // [128][NW_STR]
    float* sW2 = sW1 + 128 * NW_STR;                   // [64][NW_STR]

    const int tid = threadIdx.x, wid = tid >> 5, lane = tid & 31;
    const int g = lane >> 2, t = lane & 3;
    const int base = blockIdx.x * 128;

    // stage A = [h | SH] (tf32-rounded)
    for (int idx = tid; idx < 128 * 32; idx += 256) {
        int m = idx >> 5, k0 = (idx & 31) * 4;
        int gn = base + m;
        float4 v = make_float4(0.f, 0.f, 0.f, 0.f);
        if (gn < NN)
            v = (k0 < 64) ? *(const float4*)&g_h[gn * 64 + k0]
                          : *(const float4*)&g_SH[gn * 64 + (k0 - 64)];
        float* p = sA + m * NA_STR + k0;
        p[0] = tf32f(v.x); p[1] = tf32f(v.y); p[2] = tf32f(v.z); p[3] = tf32f(v.w);
    }
    // stage W1 rows 0..63 = nW0 (h part), 64..127 = M (SH part)
    for (int idx = tid; idx < 128 * 64; idx += 256) {
        int k = idx >> 6, n = idx & 63;
        float w = (k < 64) ? __ldg(&nW0l[k * 64 + n]) : __ldg(&Ml[(k - 64) * 64 + n]);
        sW1[k * NW_STR + n] = tf32f(w);
    }
    for (int idx = tid; idx < 64 * 64; idx += 256) {
        int k = idx >> 6, n = idx & 63;
        sW2[k * NW_STR + n] = tf32f(__ldg(&nW1l[k * 64 + n]));
    }
    __syncthreads();

    float* Aw = sA + (wid * 16) * NA_STR;   // warp-private 16 rows
    const int r0 = base + wid * 16 + g;
    const int r1 = r0 + 8;

    // ---- GEMM1: [h|SH] @ W1 ----
    float acc[8][4];
#pragma unroll
    for (int i = 0; i < 8; i++)
#pragma unroll
        for (int j = 0; j < 4; j++) acc[i][j] = 0.f;
#pragma unroll
    for (int ks = 0; ks < 16; ks++) {
        int k0 = ks * 8;
        u32 a0 = __float_as_uint(Aw[g * NA_STR + k0 + t]);
        u32 a1 = __float_as_uint(Aw[(g + 8) * NA_STR + k0 + t]);
        u32 a2 = __float_as_uint(Aw[g * NA_STR + k0 + t + 4]);
        u32 a3 = __float_as_uint(Aw[(g + 8) * NA_STR + k0 + t + 4]);
#pragma unroll
        for (int nt = 0; nt < 8; nt++) {
            u32 b0 = __float_as_uint(sW1[(k0 + t) * NW_STR + nt * 8 + g]);
            u32 b1 = __float_as_uint(sW1[(k0 + t + 4) * NW_STR + nt * 8 + g]);
            mma8(acc[nt], a0, a1, a2, a3, b0, b1);
        }
    }

    // ---- epilogue 1: hidden = elu(acc + b0 + deg*c), write into own A rows ----
    float dg0 = (r0 < NN) ? g_deg[r0] : 0.f;
    float dg1 = (r1 < NN) ? g_deg[r1] : 0.f;
#pragma unroll
    for (int nt = 0; nt < 8; nt++) {
        int c0 = nt * 8 + 2 * t, c1 = c0 + 1;
        float bb0 = __ldg(&nb0l[c0]), bb1 = __ldg(&nb0l[c1]);
        float cc0 = __ldg(&cl[c0]),   cc1 = __ldg(&cl[c1]);
        Aw[g * NA_STR + c0]       = tf32f(elu1(acc[nt][0] + bb0 + dg0 * cc0));
        Aw[g * NA_STR + c1]       = tf32f(elu1(acc[nt][1] + bb1 + dg0 * cc1));
        Aw[(g + 8) * NA_STR + c0] = tf32f(elu1(acc[nt][2] + bb0 + dg1 * cc0));
        Aw[(g + 8) * NA_STR + c1] = tf32f(elu1(acc[nt][3] + bb1 + dg1 * cc1));
    }
    __syncwarp();

    // ---- GEMM2: hidden @ W2 ----
    float acc2[8][4];
#pragma unroll
    for (int i = 0; i < 8; i++)
#pragma unroll
        for (int j = 0; j < 4; j++) acc2[i][j] = 0.f;
#pragma unroll
    for (int ks = 0; ks < 8; ks++) {
        int k0 = ks * 8;
        u32 a0 = __float_as_uint(Aw[g * NA_STR + k0 + t]);
        u32 a1 = __float_as_uint(Aw[(g + 8) * NA_STR + k0 + t]);
        u32 a2 = __float_as_uint(Aw[g * NA_STR + k0 + t + 4]);
        u32 a3 = __float_as_uint(Aw[(g + 8) * NA_STR + k0 + t + 4]);
#pragma unroll
        for (int nt = 0; nt < 8; nt++) {
            u32 b0 = __float_as_uint(sW2[(k0 + t) * NW_STR + nt * 8 + g]);
            u32 b1 = __float_as_uint(sW2[(k0 + t + 4) * NW_STR + nt * 8 + g]);
            mma8(acc2[nt], a0, a1, a2, a3, b0, b1);
        }
    }

    // ---- epilogue 2: h += acc2 + nb1 ----
#pragma unroll
    for (int nt = 0; nt < 8; nt++) {
        int c0 = nt * 8 + 2 * t, c1 = c0 + 1;
        float bb0 = __ldg(&nb1l[c0]), bb1 = __ldg(&nb1l[c1]);
        if (r0 < NN) {
            float2 prev = *(const float2*)&g_h[r0 * 64 + c0];
            *(float2*)&g_h[r0 * 64 + c0] =
                make_float2(prev.x + acc2[nt][0] + bb0, prev.y + acc2[nt][1] + bb1);
        }
        if (r1 < NN) {
            float2 prev = *(const float2*)&g_h[r1 * 64 + c0];
            *(float2*)&g_h[r1 * 64 + c0] =
                make_float2(prev.x + acc2[nt][2] + bb0, prev.y + acc2[nt][3] + bb1);
        }
    }
}

// ---------------- edge pass: gather + elu + vector scatter-add --------------
__global__ __launch_bounds__(256) void edge_kernel(const void* __restrict__ ei,
                                                   const float* __restrict__ pos,
                                                   const float* __restrict__ eb0,
                                                   int layer) {
    int t = blockIdx.x * 256 + threadIdx.x;
    int e = t >> 4, c4 = t & 15;
    if (e >= EE) return;
    int s = load_src(ei, e);
    int d = load_dst(ei, e);

    float pd0 = __ldg(&pos[s * 3 + 0]) - __ldg(&pos[d * 3 + 0]);
    float pd1 = __ldg(&pos[s * 3 + 1]) - __ldg(&pos[d * 3 + 1]);
    float pd2 = __ldg(&pos[s * 3 + 2]) - __ldg(&pos[d * 3 + 2]);

    const int j0 = c4 * 4;
    const float* P = g_P[layer];
    float4 p0 = *(const float4*)&P[j0];
    float4 p1 = *(const float4*)&P[64 + j0];
    float4 p2 = *(const float4*)&P[128 + j0];
    float4 bb = __ldg((const float4*)&eb0[layer * 64 + j0]);

    float4 va = *(const float4*)&g_hAB[s * 128 + j0];
    float4 vb = *(const float4*)&g_hAB[d * 128 + 64 + j0];

    float v0 = elu1(va.x + vb.x + bb.x + fmaf(pd0, p0.x, fmaf(pd1, p1.x, pd2 * p2.x)));
    float v1 = elu1(va.y + vb.y + bb.y + fmaf(pd0, p0.y, fmaf(pd1, p1.y, pd2 * p2.y)));
    float v2 = elu1(va.z + vb.z + bb.z + fmaf(pd0, p0.z, fmaf(pd1, p1.z, pd2 * p2.z)));
    float v3 = elu1(va.w + vb.w + bb.w + fmaf(pd0, p0.w, fmaf(pd1, p1.w, pd2 * p2.w)));

    float* dstp = &g_SH[d * 64 + j0];
    asm volatile("red.global.add.v4.f32 [%0], {%1, %2, %3, %4};"
                 :: "l"(dstp), "f"(v0), "f"(v1), "f"(v2), "f"(v3)
                 : "memory");
}

// ---------------- launch ----------------------------------------------------
extern "C" void kernel_launch(void* const* d_in, const int* in_sizes, int n_in,
                              void* d_out, int out_size) {
    const float* x      = (const float*)d_in[0];
    const float* pos    = (const float*)d_in[1];
    const void*  ei     = d_in[2];
    const float* enc_W0 = (const float*)d_in[3];
    const float* enc_b0 = (const float*)d_in[4];
    const float* enc_W1 = (const float*)d_in[5];
    const float* enc_b1 = (const float*)d_in[6];
    const float* dec_W0 = (const float*)d_in[7];
    const float* dec_b0 = (const float*)d_in[8];
    const float* dec_W1 = (const float*)d_in[9];
    const float* dec_b1 = (const float*)d_in[10];
    const float* eW0    = (const float*)d_in[11];
    const float* eb0    = (const float*)d_in[12];
    const float* eW1    = (const float*)d_in[13];
    const float* eb1    = (const float*)d_in[14];
    const float* nW0    = (const float*)d_in[15];
    const float* nb0    = (const float*)d_in[16];
    const float* nW1    = (const float*)d_in[17];
    const float* nb1    = (const float*)d_in[18];
    float* out = (float*)d_out;

    float *p_h, *p_WAB, *p_M, *p_c;
    cudaGetSymbolAddress((void**)&p_h,   g_h);
    cudaGetSymbolAddress((void**)&p_WAB, g_WAB);
    cudaGetSymbolAddress((void**)&p_M,   g_M);
    cudaGetSymbolAddress((void**)&p_c,   g_c);

    cudaFuncSetAttribute(tm_hab_kernel,
                         cudaFuncAttributeMaxDynamicSharedMemorySize, HAB_SMEMB);
    cudaFuncSetAttribute(tm_node_kernel,
                         cudaFuncAttributeMaxDynamicSharedMemorySize, ND_SMEMB);

    const int MLP_GRID = (NN + MLP_NODES - 1) / MLP_NODES;
    const int TC_GRID  = (NN + 127) / 128;

    prep_kernel<<<2, 256>>>(eW0, eW1, nW0, eb1);
    zero_kernel<<<4096, 256>>>(1);
    detect_kernel<<<(EE + 255) / 256, 256>>>((const unsigned*)ei);
    deg_kernel<<<(EE + 255) / 256, 256>>>(ei);

    // encoder (FFMA path): h = elu(x@enc_W0+b0) @ enc_W1 + b1
    mlp2_kernel<3, 64><<<MLP_GRID, MLP_THREADS>>>(
        x, enc_W0, enc_b0, enc_W1, enc_b1, p_h);

    for (int l = 0; l < 2; l++) {
        if (l) zero_kernel<<<4096, 256>>>(0);
        tm_hab_kernel<<<TC_GRID, 256, HAB_SMEMB>>>(p_WAB + l * 64 * 128);
        edge_kernel<<<(EE * 16 + 255) / 256, 256>>>(ei, pos, eb0, l);
        tm_node_kernel<<<TC_GRID, 256, ND_SMEMB>>>(
            nW0 + l * 128 * 64, p_M + l * 64 * 64, nb0 + l * 64,
            p_c + l * 64, nW1 + l * 64 * 64, nb1 + l * 64);
    }

    // decoder (FFMA path)
    mlp2_kernel<64, 3><<<MLP_GRID, MLP_THREADS>>>(
        p_h, dec_W0, dec_b0, dec_W1, dec_b1, out);
}

// round 16
// speedup vs baseline: 1.6601x; 1.6040x over previous
#include <cuda_runtime.h>
#include <math.h>

#define NN 100000
#define EE 1600000

typedef unsigned int u32;

// ---------------- scratch (static device globals; no allocations) ----------
__device__ float g_h[NN * 64];            // node features (25.6 MB)
__device__ float g_hAB[NN * 128];         // hA (cols 0..63) | hB (cols 64..127)
__device__ float g_SH[NN * 64];           // per-dst aggregated edge hidden
__device__ float g_WABP[2][72 * 128];     // [WAB ; +P|-P ; 0] extended weights
__device__ float g_M[2][64 * 64];         // eW1 @ nW0b
__device__ float g_c[2][64];              // eb1 @ nW0b
__device__ int   g_cnt[NN];               // in-degree histogram
__device__ int   g_row[NN + 1];           // CSR row pointers (by dst)
__device__ int   g_cur[NN + 1];           // scatter cursors
__device__ int   g_src[EE];               // CSR: src node per slot
__device__ int   g_i32;                   // 1 if edge_index is int32

__device__ __forceinline__ float elu1(float x) {
    return x > 0.f ? x : expm1f(x);
}
// branchless fast elu: exp2(x*log2e)-1 via MUFU, select
__device__ __forceinline__ float elu_f(float x) {
    float e;
    asm("ex2.approx.f32 %0, %1;" : "=f"(e) : "f"(x * 1.4426950408889634f));
    return x > 0.f ? x : e - 1.f;
}
__device__ __forceinline__ u32 f2tf32(float f) {
    u32 r; asm("cvt.rna.tf32.f32 %0, %1;" : "=r"(r) : "f"(f)); return r;
}
__device__ __forceinline__ float tf32f(float f) {
    return __uint_as_float(f2tf32(f));
}

// mma.sync m16n8k8 tf32 (legacy tensor-core path; compiles for base sm_103)
__device__ __forceinline__ void mma8(float* c, u32 a0, u32 a1, u32 a2, u32 a3,
                                     u32 b0, u32 b1) {
    asm volatile(
        "mma.sync.aligned.m16n8k8.row.col.f32.tf32.tf32.f32 "
        "{%0,%1,%2,%3}, {%4,%5,%6,%7}, {%8,%9}, {%0,%1,%2,%3};"
        : "+f"(c[0]), "+f"(c[1]), "+f"(c[2]), "+f"(c[3])
        : "r"(a0), "r"(a1), "r"(a2), "r"(a3), "r"(b0), "r"(b1));
}

// ---------------- prep: derived weights (tiny) ------------------------------
__global__ void prep_kernel(const float* __restrict__ eW0,
                            const float* __restrict__ eW1,
                            const float* __restrict__ nW0,
                            const float* __restrict__ eb1) {
    int l = blockIdx.x;
    int tid = threadIdx.x;
    if (l == 0 && tid == 0) g_i32 = 0;
    const float* w0 = eW0 + l * 195 * 64;
    // WABP: rows 0..63 = [Wn+Wd | Wo-Wd]; rows 64..66 = [P | -P]; 67..71 = 0
    for (int idx = tid; idx < 72 * 128; idx += 256) {
        int k = idx >> 7, j = idx & 127;
        float v;
        if (k < 64) {
            if (j < 64) v = w0[k * 64 + j] + w0[(128 + k) * 64 + j];
            else { int j2 = j - 64; v = w0[(64 + k) * 64 + j2] - w0[(128 + k) * 64 + j2]; }
        } else if (k < 67) {
            int r = k - 64;
            v = (j < 64) ? w0[(192 + r) * 64 + j] : -w0[(192 + r) * 64 + (j - 64)];
        } else v = 0.f;
        g_WABP[l][idx] = v;
    }
    const float* e1  = eW1 + l * 4096;
    const float* n0b = nW0 + l * 8192 + 64 * 64;
    for (int idx = tid; idx < 4096; idx += 256) {
        int r = idx >> 6, cc = idx & 63;
        float s = 0.f;
        for (int k = 0; k < 64; k++) s += e1[r * 64 + k] * n0b[k * 64 + cc];
        g_M[l][idx] = s;
    }
    const float* b1e = eb1 + l * 64;
    for (int idx = tid; idx < 64; idx += 256) {
        float s = 0.f;
        for (int k = 0; k < 64; k++) s += b1e[k] * n0b[k * 64 + idx];
        g_c[l][idx] = s;
    }
}

// ---------------- edge dtype detect / CSR build ------------------------------
__global__ void zcnt_kernel() {
    int i = blockIdx.x * 256 + threadIdx.x;
    if (i < NN) g_cnt[i] = 0;
}

// if int64: odd 32-bit words (high halves) are all zero. Any nonzero -> int32.
__global__ void detect_kernel(const unsigned* __restrict__ ei) {
    int i = blockIdx.x * 256 + threadIdx.x;
    if (i < EE) {
        if (ei[2 * i + 1] != 0u) g_i32 = 1;
    }
}

__device__ __forceinline__ int load_dst(const void* ei, int e) {
    if (g_i32) return ((const int*)ei)[EE + e];
    return (int)((const long long*)ei)[EE + e];
}
__device__ __forceinline__ int load_src(const void* ei, int e) {
    if (g_i32) return ((const int*)ei)[e];
    return (int)((const long long*)ei)[e];
}

__global__ __launch_bounds__(256) void hist_kernel(const void* __restrict__ ei) {
    int e = blockIdx.x * 256 + threadIdx.x;
    if (e < EE) atomicAdd(&g_cnt[load_dst(ei, e)], 1);
}

// single-block exclusive scan of g_cnt -> g_row / g_cur (1024 thr x 98 elems)
__global__ __launch_bounds__(1024) void scan_kernel() {
    __shared__ int sh[1024];
    const int tid = threadIdx.x;
    const int start = tid * 98;
    const int end = min(start + 98, NN);
    int s = 0;
    for (int i = start; i < end; i++) s += g_cnt[i];
    sh[tid] = s;
    __syncthreads();
    for (int off = 1; off < 1024; off <<= 1) {
        int v = (tid >= off) ? sh[tid - off] : 0;
        __syncthreads();
        sh[tid] += v;
        __syncthreads();
    }
    int run = (tid == 0) ? 0 : sh[tid - 1];
    for (int i = start; i < end; i++) {
        int cv = g_cnt[i];
        g_row[i] = run;
        g_cur[i] = run;
        run += cv;
    }
    if (tid == 0) { g_row[NN] = EE; g_cur[NN] = EE; }
}

__global__ __launch_bounds__(256) void scatter_kernel(const void* __restrict__ ei) {
    int e = blockIdx.x * 256 + threadIdx.x;
    if (e < EE) {
        int d = load_dst(ei, e);
        int s = load_src(ei, e);
        int slot = atomicAdd(&g_cur[d], 1);
        g_src[slot] = s;
    }
}

// ---------------- FFMA two-layer node MLP (encoder / decoder only) ----------
constexpr int MLP_NODES   = 48;
constexpr int MLP_NPAD    = 52;
constexpr int MLP_THREADS = 192;

__device__ __forceinline__ void fma16(float (&acc)[4][4], float4 xv, float4 wv) {
    float xr[4] = {xv.x, xv.y, xv.z, xv.w};
    float wr[4] = {wv.x, wv.y, wv.z, wv.w};
#pragma unroll
    for (int i = 0; i < 4; i++)
#pragma unroll
        for (int j = 0; j < 4; j++) acc[i][j] = fmaf(xr[i], wr[j], acc[i][j]);
}

template <int K1, int J2>
__global__ __launch_bounds__(MLP_THREADS)
void mlp2_kernel(const float* __restrict__ X1,
                 const float* __restrict__ W1a,
                 const float* __restrict__ b1,
                 const float* __restrict__ W2,  const float* __restrict__ b2,
                 float* __restrict__ out) {
    __shared__ float Xs[K1][MLP_NPAD];
    __shared__ float Hs[64][MLP_NPAD];

    const int tid = threadIdx.x;
    const int tj = tid & 15;
    const int tn = tid >> 4;
    const int base = blockIdx.x * MLP_NODES;
    const int n0 = tn * 4;
    const int j0 = tj * 4;

    for (int idx = tid; idx < MLP_NODES * K1; idx += MLP_THREADS) {
        int n = idx / K1, k = idx - n * K1;
        int gn = base + n;
        Xs[k][n] = (gn < NN) ? X1[gn * K1 + k] : 0.f;
    }
    __syncthreads();

    float acc[4][4];
#pragma unroll
    for (int i = 0; i < 4; i++)
#pragma unroll
        for (int j = 0; j < 4; j++) acc[i][j] = 0.f;

#pragma unroll 4
    for (int k = 0; k < K1; k++) {
        float4 xv = *(const float4*)&Xs[k][n0];
        float4 wv = __ldg((const float4*)&W1a[k * 64 + j0]);
        fma16(acc, xv, wv);
    }

    float4 bb = __ldg((const float4*)&b1[j0]);
    float bj[4] = {bb.x, bb.y, bb.z, bb.w};
    float hid[4][4];
#pragma unroll
    for (int i = 0; i < 4; i++)
#pragma unroll
        for (int j = 0; j < 4; j++)
            hid[i][j] = elu1(acc[i][j] + bj[j]);
#pragma unroll
    for (int jj = 0; jj < 4; jj++) {
        float4 hv = make_float4(hid[0][jj], hid[1][jj], hid[2][jj], hid[3][jj]);
        *(float4*)&Hs[j0 + jj][n0] = hv;
    }
    __syncthreads();

    if constexpr (J2 == 64) {
        float a2[4][4];
#pragma unroll
        for (int i = 0; i < 4; i++)
#pragma unroll
            for (int j = 0; j < 4; j++) a2[i][j] = 0.f;
#pragma unroll 4
        for (int k = 0; k < 64; k++) {
            float4 xv = *(const float4*)&Hs[k][n0];
            float4 wv = __ldg((const float4*)&W2[k * 64 + j0]);
            fma16(a2, xv, wv);
        }
        float4 b2v = __ldg((const float4*)&b2[j0]);
#pragma unroll
        for (int i = 0; i < 4; i++) {
            int gn = base + n0 + i;
            if (gn < NN) {
                float4 o;
                o.x = a2[i][0] + b2v.x;
                o.y = a2[i][1] + b2v.y;
                o.z = a2[i][2] + b2v.z;
                o.w = a2[i][3] + b2v.w;
                *(float4*)&out[gn * 64 + j0] = o;
            }
        }
    } else {  // J2 == 3 decoder
        float a3[4][3] = {};
#pragma unroll
        for (int kk = 0; kk < 4; kk++) {
            int k = j0 + kk;
            float4 hv = *(const float4*)&Hs[k][n0];
            float hr[4] = {hv.x, hv.y, hv.z, hv.w};
#pragma unroll
            for (int j = 0; j < 3; j++) {
                float w = __ldg(&W2[k * 3 + j]);
#pragma unroll
                for (int i = 0; i < 4; i++) a3[i][j] = fmaf(hr[i], w, a3[i][j]);
            }
        }
#pragma unroll
        for (int off = 8; off; off >>= 1)
#pragma unroll
            for (int i = 0; i < 4; i++)
#pragma unroll
                for (int j = 0; j < 3; j++)
                    a3[i][j] += __shfl_down_sync(0xffffffffu, a3[i][j], off, 16);
        if (tj == 0) {
#pragma unroll
            for (int i = 0; i < 4; i++) {
                int gn = base + n0 + i;
                if (gn < NN)
#pragma unroll
                    for (int j = 0; j < 3; j++)
                        out[gn * 3 + j] = a3[i][j] + __ldg(&b2[j]);
            }
        }
    }
}

// ======================= mma.sync hAB kernel (K=72) =========================
// hAB[m,0:128] = [h|pos|0] @ WABP[72,128]; epilogue adds eb0 to cols 0..63.
constexpr int HK     = 72;
constexpr int HA_STR = 76;    // 76 % 32 == 12 -> conflict-free A frags
constexpr int HW_STR = 136;   // 136 % 32 == 8 -> conflict-free B frags
constexpr int HAB_SMEMB = (128 * HA_STR + HK * HW_STR) * 4;

__global__ __launch_bounds__(256, 1) void tm_hab_kernel(
    const float* __restrict__ Wabp, const float* __restrict__ pos,
    const float* __restrict__ eb0l) {
    extern __shared__ float smf[];
    float* sA = smf;                       // [128][HA_STR], k = 0..71
    float* sW = smf + 128 * HA_STR;        // [72][HW_STR],  n = 0..127

    const int tid = threadIdx.x, wid = tid >> 5, lane = tid & 31;
    const int g = lane >> 2, t = lane & 3;
    const int base = blockIdx.x * 128;

    for (int idx = tid; idx < 128 * 16; idx += 256) {
        int m = idx >> 4, k0 = (idx & 15) * 4;
        int gn = base + m;
        float4 v = make_float4(0.f, 0.f, 0.f, 0.f);
        if (gn < NN) v = *(const float4*)&g_h[gn * 64 + k0];
        float* p = sA + m * HA_STR + k0;
        p[0] = tf32f(v.x); p[1] = tf32f(v.y); p[2] = tf32f(v.z); p[3] = tf32f(v.w);
    }
    // cols 64..71: [pos0,pos1,pos2,0,0,0,0,0]
    for (int idx = tid; idx < 128 * 2; idx += 256) {
        int m = idx >> 1, half = idx & 1;
        int gn = base + m;
        float* p = sA + m * HA_STR + 64 + half * 4;
        if (half == 0 && gn < NN) {
            p[0] = tf32f(__ldg(&pos[gn * 3 + 0]));
            p[1] = tf32f(__ldg(&pos[gn * 3 + 1]));
            p[2] = tf32f(__ldg(&pos[gn * 3 + 2]));
            p[3] = 0.f;
        } else {
            p[0] = 0.f; p[1] = 0.f; p[2] = 0.f; p[3] = 0.f;
        }
    }
    for (int idx = tid; idx < HK * 128; idx += 256) {
        int k = idx >> 7, n = idx & 127;
        sW[k * HW_STR + n] = tf32f(__ldg(&Wabp[k * 128 + n]));
    }
    __syncthreads();

    const float* Aw = sA + (wid * 16) * HA_STR;
    float acc[16][4];
#pragma unroll
    for (int i = 0; i < 16; i++)
#pragma unroll
        for (int j = 0; j < 4; j++) acc[i][j] = 0.f;

#pragma unroll
    for (int ks = 0; ks < 9; ks++) {
        int k0 = ks * 8;
        u32 a0 = __float_as_uint(Aw[g * HA_STR + k0 + t]);
        u32 a1 = __float_as_uint(Aw[(g + 8) * HA_STR + k0 + t]);
        u32 a2 = __float_as_uint(Aw[g * HA_STR + k0 + t + 4]);
        u32 a3 = __float_as_uint(Aw[(g + 8) * HA_STR + k0 + t + 4]);
#pragma unroll
        for (int nt = 0; nt < 16; nt++) {
            u32 b0 = __float_as_uint(sW[(k0 + t) * HW_STR + nt * 8 + g]);
            u32 b1 = __float_as_uint(sW[(k0 + t + 4) * HW_STR + nt * 8 + g]);
            mma8(acc[nt], a0, a1, a2, a3, b0, b1);
        }
    }

    const int r0 = base + wid * 16 + g;
    const int r1 = r0 + 8;
#pragma unroll
    for (int nt = 0; nt < 16; nt++) {
        int col = nt * 8 + 2 * t;
        float e0 = 0.f, e1 = 0.f;
        if (nt < 8) { e0 = __ldg(&eb0l[col]); e1 = __ldg(&eb0l[col + 1]); }
        if (r0 < NN) *(float2*)&g_hAB[r0 * 128 + col] =
            make_float2(acc[nt][0] + e0, acc[nt][1] + e1);
        if (r1 < NN) *(float2*)&g_hAB[r1 * 128 + col] =
            make_float2(acc[nt][2] + e0, acc[nt][3] + e1);
    }
}

// ======================= CSR edge aggregation (no atomics) ==================
// SH[d] = sum_{e: dst=d} elu(hA[src[e]] + hB[d]);  16 threads per dst.
__global__ __launch_bounds__(256) void edge_csr_kernel() {
    int tt = blockIdx.x * 256 + threadIdx.x;
    int d = tt >> 4, j0 = (tt & 15) * 4;
    if (d >= NN) return;
    int e0 = g_row[d], e1 = g_row[d + 1];

    float4 vb = *(const float4*)&g_hAB[d * 128 + 64 + j0];
    float a0 = 0.f, a1 = 0.f, a2 = 0.f, a3 = 0.f;
    float b0 = 0.f, b1 = 0.f, b2 = 0.f, b3 = 0.f;

    int e = e0;
    for (; e + 1 < e1; e += 2) {
        int s0 = __ldg(&g_src[e]);
        int s1 = __ldg(&g_src[e + 1]);
        float4 u = __ldg((const float4*)&g_hAB[s0 * 128 + j0]);
        float4 w = __ldg((const float4*)&g_hAB[s1 * 128 + j0]);
        a0 += elu_f(u.x + vb.x); a1 += elu_f(u.y + vb.y);
        a2 += elu_f(u.z + vb.z); a3 += elu_f(u.w + vb.w);
        b0 += elu_f(w.x + vb.x); b1 += elu_f(w.y + vb.y);
        b2 += elu_f(w.z + vb.z); b3 += elu_f(w.w + vb.w);
    }
    if (e < e1) {
        int s0 = __ldg(&g_src[e]);
        float4 u = __ldg((const float4*)&g_hAB[s0 * 128 + j0]);
        a0 += elu_f(u.x + vb.x); a1 += elu_f(u.y + vb.y);
        a2 += elu_f(u.z + vb.z); a3 += elu_f(u.w + vb.w);
    }
    *(float4*)&g_SH[d * 64 + j0] = make_float4(a0 + b0, a1 + b1, a2 + b2, a3 + b3);
}

// ======================= mma.sync fused node-update kernel ==================
// h += elu([h|SH] @ W1 + deg*c + b0) @ W2 + b1   (K1=128 -> N=64, K2=64 -> N=64)
constexpr int NA_STR = 132;   // 132 % 32 == 4
constexpr int NW_STR = 72;    // 72  % 32 == 8
constexpr int ND_SMEMB = (128 * NA_STR + 128 * NW_STR + 64 * NW_STR) * 4;

__global__ __launch_bounds__(256, 1) void tm_node_kernel(
    const float* __restrict__ nW0l, const float* __restrict__ Ml,
    const float* __restrict__ nb0l, const float* __restrict__ cl,
    const float* __restrict__ nW1l, const float* __restrict__ nb1l) {
    extern __shared__ float smf[];
    float* sA  = smf;                                  // [128][NA_STR]
    float* sW1 = smf + 128 * NA_STR;                   // [128][NW_STR]
    float* sW2 = sW1 + 128 * NW_STR;                   // [64][NW_STR]

    const int tid = threadIdx.x, wid = tid >> 5, lane = tid & 31;
    const int g = lane >> 2, t = lane & 3;
    const int base = blockIdx.x * 128;

    for (int idx = tid; idx < 128 * 32; idx += 256) {
        int m = idx >> 5, k0 = (idx & 31) * 4;
        int gn = base + m;
        float4 v = make_float4(0.f, 0.f, 0.f, 0.f);
        if (gn < NN)
            v = (k0 < 64) ? *(const float4*)&g_h[gn * 64 + k0]
                          : *(const float4*)&g_SH[gn * 64 + (k0 - 64)];
        float* p = sA + m * NA_STR + k0;
        p[0] = tf32f(v.x); p[1] = tf32f(v.y); p[2] = tf32f(v.z); p[3] = tf32f(v.w);
    }
    for (int idx = tid; idx < 128 * 64; idx += 256) {
        int k = idx >> 6, n = idx & 63;
        float w = (k < 64) ? __ldg(&nW0l[k * 64 + n]) : __ldg(&Ml[(k - 64) * 64 + n]);
        sW1[k * NW_STR + n] = tf32f(w);
    }
    for (int idx = tid; idx < 64 * 64; idx += 256) {
        int k = idx >> 6, n = idx & 63;
        sW2[k * NW_STR + n] = tf32f(__ldg(&nW1l[k * 64 + n]));
    }
    __syncthreads();

    float* Aw = sA + (wid * 16) * NA_STR;   // warp-private 16 rows
    const int r0 = base + wid * 16 + g;
    const int r1 = r0 + 8;

    // ---- GEMM1: [h|SH] @ W1 ----
    float acc[8][4];
#pragma unroll
    for (int i = 0; i < 8; i++)
#pragma unroll
        for (int j = 0; j < 4; j++) acc[i][j] = 0.f;
#pragma unroll
    for (int ks = 0; ks < 16; ks++) {
        int k0 = ks * 8;
        u32 a0 = __float_as_uint(Aw[g * NA_STR + k0 + t]);
        u32 a1 = __float_as_uint(Aw[(g + 8) * NA_STR + k0 + t]);
        u32 a2 = __float_as_uint(Aw[g * NA_STR + k0 + t + 4]);
        u32 a3 = __float_as_uint(Aw[(g + 8) * NA_STR + k0 + t + 4]);
#pragma unroll
        for (int nt = 0; nt < 8; nt++) {
            u32 b0 = __float_as_uint(sW1[(k0 + t) * NW_STR + nt * 8 + g]);
            u32 b1 = __float_as_uint(sW1[(k0 + t + 4) * NW_STR + nt * 8 + g]);
            mma8(acc[nt], a0, a1, a2, a3, b0, b1);
        }
    }

    // ---- epilogue 1: hidden = elu(acc + b0 + deg*c) into own A rows ----
    float dg0 = (r0 < NN) ? (float)(g_row[r0 + 1] - g_row[r0]) : 0.f;
    float dg1 = (r1 < NN) ? (float)(g_row[r1 + 1] - g_row[r1]) : 0.f;
#pragma unroll
    for (int nt = 0; nt < 8; nt++) {
        int c0 = nt * 8 + 2 * t, c1 = c0 + 1;
        float bb0 = __ldg(&nb0l[c0]), bb1 = __ldg(&nb0l[c1]);
        float cc0 = __ldg(&cl[c0]),   cc1 = __ldg(&cl[c1]);
        Aw[g * NA_STR + c0]       = tf32f(elu1(acc[nt][0] + bb0 + dg0 * cc0));
        Aw[g * NA_STR + c1]       = tf32f(elu1(acc[nt][1] + bb1 + dg0 * cc1));
        Aw[(g + 8) * NA_STR + c0] = tf32f(elu1(acc[nt][2] + bb0 + dg1 * cc0));
        Aw[(g + 8) * NA_STR + c1] = tf32f(elu1(acc[nt][3] + bb1 + dg1 * cc1));
    }
    __syncwarp();

    // ---- GEMM2: hidden @ W2 ----
    float acc2[8][4];
#pragma unroll
    for (int i = 0; i < 8; i++)
#pragma unroll
        for (int j = 0; j < 4; j++) acc2[i][j] = 0.f;
#pragma unroll
    for (int ks = 0; ks < 8; ks++) {
        int k0 = ks * 8;
        u32 a0 = __float_as_uint(Aw[g * NA_STR + k0 + t]);
        u32 a1 = __float_as_uint(Aw[(g + 8) * NA_STR + k0 + t]);
        u32 a2 = __float_as_uint(Aw[g * NA_STR + k0 + t + 4]);
        u32 a3 = __float_as_uint(Aw[(g + 8) * NA_STR + k0 + t + 4]);
#pragma unroll
        for (int nt = 0; nt < 8; nt++) {
            u32 b0 = __float_as_uint(sW2[(k0 + t) * NW_STR + nt * 8 + g]);
            u32 b1 = __float_as_uint(sW2[(k0 + t + 4) * NW_STR + nt * 8 + g]);
            mma8(acc2[nt], a0, a1, a2, a3, b0, b1);
        }
    }

    // ---- epilogue 2: h += acc2 + nb1 ----
#pragma unroll
    for (int nt = 0; nt < 8; nt++) {
        int c0 = nt * 8 + 2 * t, c1 = c0 + 1;
        float bb0 = __ldg(&nb1l[c0]), bb1 = __ldg(&nb1l[c1]);
        if (r0 < NN) {
            float2 prev = *(const float2*)&g_h[r0 * 64 + c0];
            *(float2*)&g_h[r0 * 64 + c0] =
                make_float2(prev.x + acc2[nt][0] + bb0, prev.y + acc2[nt][1] + bb1);
        }
        if (r1 < NN) {
            float2 prev = *(const float2*)&g_h[r1 * 64 + c0];
            *(float2*)&g_h[r1 * 64 + c0] =
                make_float2(prev.x + acc2[nt][2] + bb0, prev.y + acc2[nt][3] + bb1);
        }
    }
}

// ---------------- launch ----------------------------------------------------
extern "C" void kernel_launch(void* const* d_in, const int* in_sizes, int n_in,
                              void* d_out, int out_size) {
    const float* x      = (const float*)d_in[0];
    const float* pos    = (const float*)d_in[1];
    const void*  ei     = d_in[2];
    const float* enc_W0 = (const float*)d_in[3];
    const float* enc_b0 = (const float*)d_in[4];
    const float* enc_W1 = (const float*)d_in[5];
    const float* enc_b1 = (const float*)d_in[6];
    const float* dec_W0 = (const float*)d_in[7];
    const float* dec_b0 = (const float*)d_in[8];
    const float* dec_W1 = (const float*)d_in[9];
    const float* dec_b1 = (const float*)d_in[10];
    const float* eW0    = (const float*)d_in[11];
    const float* eb0    = (const float*)d_in[12];
    const float* eW1    = (const float*)d_in[13];
    const float* eb1    = (const float*)d_in[14];
    const float* nW0    = (const float*)d_in[15];
    const float* nb0    = (const float*)d_in[16];
    const float* nW1    = (const float*)d_in[17];
    const float* nb1    = (const float*)d_in[18];
    float* out = (float*)d_out;

    float *p_h, *p_WABP, *p_M, *p_c;
    cudaGetSymbolAddress((void**)&p_h,    g_h);
    cudaGetSymbolAddress((void**)&p_WABP, g_WABP);
    cudaGetSymbolAddress((void**)&p_M,    g_M);
    cudaGetSymbolAddress((void**)&p_c,    g_c);

    cudaFuncSetAttribute(tm_hab_kernel,
                         cudaFuncAttributeMaxDynamicSharedMemorySize, HAB_SMEMB);
    cudaFuncSetAttribute(tm_node_kernel,
                         cudaFuncAttributeMaxDynamicSharedMemorySize, ND_SMEMB);

    const int MLP_GRID = (NN + MLP_NODES - 1) / MLP_NODES;
    const int TC_GRID  = (NN + 127) / 128;
    const int E_GRID   = (EE + 255) / 256;

    prep_kernel<<<2, 256>>>(eW0, eW1, nW0, eb1);
    zcnt_kernel<<<(NN + 255) / 256, 256>>>();
    detect_kernel<<<E_GRID, 256>>>((const unsigned*)ei);
    hist_kernel<<<E_GRID, 256>>>(ei);
    scan_kernel<<<1, 1024>>>();
    scatter_kernel<<<E_GRID, 256>>>(ei);

    // encoder (FFMA path): h = elu(x@enc_W0+b0) @ enc_W1 + b1
    mlp2_kernel<3, 64><<<MLP_GRID, MLP_THREADS>>>(
        x, enc_W0, enc_b0, enc_W1, enc_b1, p_h);

    for (int l = 0; l < 2; l++) {
        tm_hab_kernel<<<TC_GRID, 256, HAB_SMEMB>>>(
            p_WABP + l * 72 * 128, pos, eb0 + l * 64);
        edge_csr_kernel<<<(NN * 16 + 255) / 256, 256>>>();
        tm_node_kernel<<<TC_GRID, 256, ND_SMEMB>>>(
            nW0 + l * 128 * 64, p_M + l * 64 * 64, nb0 + l * 64,
            p_c + l * 64, nW1 + l * 64 * 64, nb1 + l * 64);
    }

    // decoder (FFMA path)
    mlp2_kernel<64, 3><<<MLP_GRID, MLP_THREADS>>>(
        p_h, dec_W0, dec_b0, dec_W1, dec_b1, out);
}